// round 15
// baseline (speedup 1.0000x reference)
#include <cuda_runtime.h>
#include <cuda_fp16.h>
#include <math.h>

#define TLEN   4096
#define TOK    32768
#define CH     256
#define CH2    512
#define SPECT  640
#define KCONV  768
#define KTOT   1408
#define NLAYERS 12
#define SA     24          // smem k-stride (elems), padded vs. bank conflicts

typedef unsigned int u32;

// ------------------------- device scratch (alloc-free rule) -----------------
__device__ float g_started[TOK*CH];
__device__ float g_skip[TOK*CH];
__device__ __half g_sh[TOK*CH],   g_sl[TOK*CH];     // started hi/lo (fp16)
__device__ __half g_ah[TOK*CH],   g_al[TOK*CH];     // activated hi/lo
__device__ __half g_xh[TOK*SPECT],g_xl[TOK*SPECT];  // spect hi/lo
__device__ __half g_bgh[NLAYERS*CH2*KTOT];          // gate W^T [l][n][k], fp16
__device__ __half g_brh[(NLAYERS-1)*CH2*CH];        // res W^T
__device__ __half g_blh[CH*CH];                     // last res W^T

__device__ __forceinline__ void split2h(float v, __half& h, __half& l){
    h = __float2half(v);
    l = __float2half(v - __half2float(h));
}
__device__ __forceinline__ u32 smem_u32(const void* p){
    u32 a; asm("{ .reg .u64 t; cvta.to.shared.u64 t, %1; cvt.u32.u64 %0, t; }"
               : "=r"(a) : "l"(p));
    return a;
}
__device__ __forceinline__ void mma_f16(float* c, const u32* a, const u32* b){
    asm volatile(
      "mma.sync.aligned.m16n8k16.row.col.f32.f16.f16.f32 "
      "{%0,%1,%2,%3}, {%4,%5,%6,%7}, {%8,%9}, {%0,%1,%2,%3};\n"
      : "+f"(c[0]), "+f"(c[1]), "+f"(c[2]), "+f"(c[3])
      : "r"(a[0]), "r"(a[1]), "r"(a[2]), "r"(a[3]), "r"(b[0]), "r"(b[1]));
}
__device__ __forceinline__ void cpa16(u32 dst, const void* src, u32 sz){
    asm volatile("cp.async.cg.shared.global [%0], [%1], 16, %2;\n"
                 :: "r"(dst), "l"(src), "r"(sz));
}
__device__ __forceinline__ void cpa_commit(){ asm volatile("cp.async.commit_group;\n"); }
__device__ __forceinline__ void cpa_wait(){ asm volatile("cp.async.wait_group 0;\n"); }

// ------------------------------ prep kernels --------------------------------
__global__ void prep_spect_kernel(const float* __restrict__ spect){
    int i = blockIdx.x*256 + threadIdx.x;
    if (i >= TOK*SPECT) return;
    split2h(spect[i], g_xh[i], g_xl[i]);
}
__global__ void prep_gateB_kernel(const float* __restrict__ w_in,
                                  const float* __restrict__ w_cond){
    long i = (long)blockIdx.x*256 + threadIdx.x;
    if (i >= (long)NLAYERS*CH2*KTOT) return;
    int kk = (int)(i % KTOT);
    long r = i / KTOT;
    int n  = (int)(r % CH2);
    int l  = (int)(r / CH2);
    float v = (kk < KCONV) ? w_in[((size_t)l*KCONV + kk)*CH2 + n]
                           : w_cond[((size_t)l*SPECT + (kk-KCONV))*CH2 + n];
    g_bgh[i] = __float2half(v);
}
__global__ void prep_resB_kernel(const float* __restrict__ w_res,
                                 const float* __restrict__ w_res_last){
    int i = blockIdx.x*256 + threadIdx.x;
    const int NRES = (NLAYERS-1)*CH2*CH;
    if (i < NRES){
        int k = i % CH;
        int r = i / CH;
        int n = r % CH2;
        int l = r / CH2;
        g_brh[i] = __float2half(w_res[((size_t)l*CH + k)*CH2 + n]);
    } else if (i < NRES + CH*CH){
        int j = i - NRES;
        int k = j % CH;
        int n = j / CH;
        g_blh[j] = __float2half(w_res_last[(size_t)k*CH + n]);
    }
}

// ------------------------------ start kernel --------------------------------
__global__ void start_kernel(const float* __restrict__ audio,
                             const float* __restrict__ w_start,
                             const float* __restrict__ b_start)
{
    int idx = blockIdx.x*256 + threadIdx.x;
    if (idx >= TOK*CH) return;
    int token = idx >> 8;
    int c     = idx & 255;
    const float* a = audio + token*4;
    float v = b_start[c];
    v += a[0]*w_start[0*CH + c];
    v += a[1]*w_start[1*CH + c];
    v += a[2]*w_start[2*CH + c];
    v += a[3]*w_start[3*CH + c];
    g_started[idx] = v;
    split2h(v, g_sh[idx], g_sl[idx]);
    g_skip[idx] = 0.f;
}

// ------------------------------ gate kernel ---------------------------------
// Block: 128 tokens x (64 tanh cols + 64 sig cols). K=1408 = 88 chunks of 16.
// conv K-part (stages 0..47):  2-limb  acc += Ahi*Bh + Alo*Bh
// cond K-part (stages 48..87): 1-limb  acc += Ahi*Bh      (spect is static input)
__global__ void __launch_bounds__(256,2) gate_kernel(
    const float* __restrict__ b_in, const float* __restrict__ b_cond,
    int layer, int dil)
{
    __shared__ __half sm[2][3][128*SA]; // [buf][Ah,Al,Bh][row*SA+k]

    int tid = threadIdx.x;
    int m0 = blockIdx.x*128;
    int n0 = blockIdx.y*64;          // tanh column base (0,64,128,192)
    int warp = tid>>5, lane = tid&31;
    int wm = warp>>1, wn = warp&1;
    int g = lane>>2,  tig = lane&3;

    u32 sbase = smem_u32(sm);

    // tile-load mapping: 2 threads per row, each 16B (8 halves) per plane
    int lrow = tid>>1, lhalf = tid&1;
    int token = m0 + lrow;
    int bb = token>>12, tt = token&(TLEN-1);
    int cw = lrow>>6, cc2 = lrow&63;
    int ncol = (cc2<32) ? (n0 + cw*32 + cc2) : (256 + n0 + cw*32 + (cc2-32));
    const __half* browh = g_bgh + ((size_t)layer*CH2 + ncol)*KTOT + lhalf*8;

    // precomputed per-thread A sources: 3 taps + spect
    const __half* tapH[3];
    const __half* tapL[3];
    u32 tapSz[3];
    #pragma unroll
    for (int t=0;t<3;t++){
        int ts = tt + (t-1)*dil;
        bool ok = ((unsigned)ts < (unsigned)TLEN);
        int tok2 = (bb<<12) + (ok ? ts : 0);
        tapH[t] = g_sh + ((size_t)tok2<<8) + lhalf*8;
        tapL[t] = g_sl + ((size_t)tok2<<8) + lhalf*8;
        tapSz[t] = ok ? 16u : 0u;
    }
    const __half* xH = g_xh + (size_t)token*SPECT + lhalf*8;

    const u32 PLB = 128*SA*2;
    u32 doff = (u32)(lrow*SA + lhalf*8)*2;

    auto load_tiles = [&](int kc, int buf){
        u32 pb = sbase + (u32)buf*3u*PLB;
        if (kc < 48){
            int tap = kc>>4;
            int ch  = (kc&15)<<4;
            cpa16(pb       + doff, tapH[tap] + ch, tapSz[tap]);
            cpa16(pb + PLB + doff, tapL[tap] + ch, tapSz[tap]);
        } else {
            int koff = (kc-48)<<4;
            cpa16(pb       + doff, xH + koff, 16u);
        }
        cpa16(pb + 2*PLB + doff, browh + (kc<<4), 16u);
        cpa_commit();
    };

    float acc[2][8][4];
    #pragma unroll
    for (int mt=0;mt<2;mt++)
        #pragma unroll
        for (int j=0;j<8;j++)
            #pragma unroll
            for (int r2=0;r2<4;r2++) acc[mt][j][r2]=0.f;

    load_tiles(0,0);
    const int NKC = KTOT/16;
    for (int kc=0; kc<NKC; kc++){
        cpa_wait(); __syncthreads();
        if (kc+1 < NKC) load_tiles(kc+1, (kc+1)&1);
        int buf = kc&1;
        bool conv = (kc < 48);

        u32 fa[2][2][4]; // [limb][mtile][reg]
        #pragma unroll
        for (int mt=0; mt<2; mt++){
            int r0 = (wm*32 + mt*16 + g)*SA + 2*tig;
            const __half* ph = &sm[buf][0][r0];
            fa[0][mt][0] = *(const u32*)(ph);
            fa[0][mt][1] = *(const u32*)(ph + 8*SA);
            fa[0][mt][2] = *(const u32*)(ph + 8);
            fa[0][mt][3] = *(const u32*)(ph + 8*SA + 8);
        }
        if (conv){
            #pragma unroll
            for (int mt=0; mt<2; mt++){
                int r0 = (wm*32 + mt*16 + g)*SA + 2*tig;
                const __half* pl = &sm[buf][1][r0];
                fa[1][mt][0] = *(const u32*)(pl);
                fa[1][mt][1] = *(const u32*)(pl + 8*SA);
                fa[1][mt][2] = *(const u32*)(pl + 8);
                fa[1][mt][3] = *(const u32*)(pl + 8*SA + 8);
            }
        }
        #pragma unroll
        for (int j=0; j<8; j++){
            int cr = (wn*64 + j*8 + g)*SA + 2*tig;
            const __half* pbh = &sm[buf][2][cr];
            u32 bh[2] = { *(const u32*)pbh, *(const u32*)(pbh+8) };
            mma_f16(acc[0][j], fa[0][0], bh);
            mma_f16(acc[1][j], fa[0][1], bh);
            if (conv){
                mma_f16(acc[0][j], fa[1][0], bh);
                mma_f16(acc[1][j], fa[1][1], bh);
            }
        }
    }

    // epilogue: acc[mt][j] = tanh half, acc[mt][j+4] = matching sigmoid half
    #pragma unroll
    for (int mt=0; mt<2; mt++){
        #pragma unroll
        for (int j=0; j<4; j++){
            int ct = n0 + wn*32 + j*8 + 2*tig;
            float bT0 = b_in[ct]     + b_cond[ct];
            float bT1 = b_in[ct+1]   + b_cond[ct+1];
            float bS0 = b_in[ct+256] + b_cond[ct+256];
            float bS1 = b_in[ct+257] + b_cond[ct+257];
            #pragma unroll
            for (int h=0; h<2; h++){
                int row = m0 + wm*32 + mt*16 + g + h*8;
                float t0 = acc[mt][j][h*2+0] + bT0;
                float t1 = acc[mt][j][h*2+1] + bT1;
                float s0 = acc[mt][j+4][h*2+0] + bS0;
                float s1 = acc[mt][j+4][h*2+1] + bS1;
                float v0 = tanhf(t0) * (1.f/(1.f+__expf(-s0)));
                float v1 = tanhf(t1) * (1.f/(1.f+__expf(-s1)));
                __half h0,l0,h1,l1;
                split2h(v0,h0,l0); split2h(v1,h1,l1);
                size_t o = (size_t)row*CH + ct;
                __half2 vh; vh.x=h0; vh.y=h1;
                __half2 vl; vl.x=l0; vl.y=l1;
                *(__half2*)&g_ah[o] = vh;
                *(__half2*)&g_al[o] = vl;
            }
        }
    }
}

// ------------------------------ res kernel ----------------------------------
// rs = activated @ w + bias; cols<256 -> started update (+ re-split),
// cols>=256 -> skip accumulation. last: all 256 cols -> skip.
__global__ void __launch_bounds__(256,2) res_kernel(
    const float* __restrict__ bias, int layer, int last)
{
    __shared__ __half sm[2][3][128*SA];

    int tid = threadIdx.x;
    int m0 = blockIdx.x*128;
    int n0 = blockIdx.y*128;
    int warp = tid>>5, lane = tid&31;
    int wm = warp>>1, wn = warp&1;
    int g = lane>>2,  tig = lane&3;

    u32 sbase = smem_u32(sm);

    int lrow = tid>>1, lhalf = tid&1;
    int token = m0 + lrow;
    int ncol = n0 + lrow;
    const __half* browh = (last ? (g_blh + (size_t)ncol*CH)
                                : (g_brh + ((size_t)layer*CH2 + ncol)*CH)) + lhalf*8;
    const __half* arh = g_ah + (size_t)token*CH + lhalf*8;
    const __half* arl = g_al + (size_t)token*CH + lhalf*8;

    const u32 PLB = 128*SA*2;
    u32 doff = (u32)(lrow*SA + lhalf*8)*2;

    auto load_tiles = [&](int kc, int buf){
        u32 pb = sbase + (u32)buf*3u*PLB;
        int kb = kc<<4;
        cpa16(pb         + doff, arh + kb, 16u);
        cpa16(pb + PLB   + doff, arl + kb, 16u);
        cpa16(pb + 2*PLB + doff, browh + kb, 16u);
        cpa_commit();
    };

    float acc[2][8][4];
    #pragma unroll
    for (int mt=0;mt<2;mt++)
        #pragma unroll
        for (int j=0;j<8;j++)
            #pragma unroll
            for (int r2=0;r2<4;r2++) acc[mt][j][r2]=0.f;

    load_tiles(0,0);
    const int NKC = CH/16;
    for (int kc=0; kc<NKC; kc++){
        cpa_wait(); __syncthreads();
        if (kc+1 < NKC) load_tiles(kc+1, (kc+1)&1);
        int buf = kc&1;

        u32 fa[2][2][4];
        #pragma unroll
        for (int mt=0; mt<2; mt++){
            int r0 = (wm*32 + mt*16 + g)*SA + 2*tig;
            const __half* ph = &sm[buf][0][r0];
            fa[0][mt][0] = *(const u32*)(ph);
            fa[0][mt][1] = *(const u32*)(ph + 8*SA);
            fa[0][mt][2] = *(const u32*)(ph + 8);
            fa[0][mt][3] = *(const u32*)(ph + 8*SA + 8);
            const __half* pl = &sm[buf][1][r0];
            fa[1][mt][0] = *(const u32*)(pl);
            fa[1][mt][1] = *(const u32*)(pl + 8*SA);
            fa[1][mt][2] = *(const u32*)(pl + 8);
            fa[1][mt][3] = *(const u32*)(pl + 8*SA + 8);
        }
        #pragma unroll
        for (int j=0; j<8; j++){
            int cr = (wn*64 + j*8 + g)*SA + 2*tig;
            const __half* pbh = &sm[buf][2][cr];
            u32 bh[2] = { *(const u32*)pbh, *(const u32*)(pbh+8) };
            mma_f16(acc[0][j], fa[0][0], bh);
            mma_f16(acc[1][j], fa[0][1], bh);
            mma_f16(acc[0][j], fa[1][0], bh);
            mma_f16(acc[1][j], fa[1][1], bh);
        }
    }

    #pragma unroll
    for (int mt=0; mt<2; mt++){
        #pragma unroll
        for (int j=0; j<8; j++){
            int col = n0 + wn*64 + j*8 + 2*tig;
            float b0v = bias[col], b1v = bias[col+1];
            #pragma unroll
            for (int h=0; h<2; h++){
                int row = m0 + wm*32 + mt*16 + g + h*8;
                float v0 = acc[mt][j][h*2+0] + b0v;
                float v1 = acc[mt][j][h*2+1] + b1v;
                if (last){
                    size_t o = (size_t)row*CH + col;
                    g_skip[o]   += v0;
                    g_skip[o+1] += v1;
                } else if (col < 256){
                    size_t o = (size_t)row*CH + col;
                    float s0 = g_started[o]   + v0;
                    float s1 = g_started[o+1] + v1;
                    g_started[o]   = s0;
                    g_started[o+1] = s1;
                    __half h0,l0,h1,l1;
                    split2h(s0,h0,l0); split2h(s1,h1,l1);
                    __half2 vh; vh.x=h0; vh.y=h1;
                    __half2 vl; vl.x=l0; vl.y=l1;
                    *(__half2*)&g_sh[o] = vh;
                    *(__half2*)&g_sl[o] = vl;
                } else {
                    size_t o = (size_t)row*CH + col - 256;
                    g_skip[o]   += v0;
                    g_skip[o+1] += v1;
                }
            }
        }
    }
}

// ------------------------------ end kernel ----------------------------------
__global__ void end_kernel(const float* __restrict__ w_end,
                           const float* __restrict__ b_end,
                           float* __restrict__ out)
{
    int idx = blockIdx.x*256 + threadIdx.x;
    if (idx >= TOK*8) return;
    int token = idx >> 3;
    int j     = idx & 7;
    const float* s = g_skip + (size_t)token*CH;
    float v = b_end[j];
    #pragma unroll 8
    for (int c = 0; c < CH; c++)
        v += s[c] * w_end[c*8 + j];
    out[idx] = v;
}

// ----------------------------------------------------------------------------
extern "C" void kernel_launch(void* const* d_in, const int* in_sizes, int n_in,
                              void* d_out, int out_size)
{
    const float* audio      = (const float*)d_in[0];
    const float* spect      = (const float*)d_in[1];
    const float* w_start    = (const float*)d_in[2];
    const float* b_start    = (const float*)d_in[3];
    const float* w_in       = (const float*)d_in[4];
    const float* b_in       = (const float*)d_in[5];
    const float* w_cond     = (const float*)d_in[6];
    const float* b_cond     = (const float*)d_in[7];
    const float* w_res      = (const float*)d_in[8];
    const float* b_res      = (const float*)d_in[9];
    const float* w_res_last = (const float*)d_in[10];
    const float* b_res_last = (const float*)d_in[11];
    const float* w_end      = (const float*)d_in[12];
    const float* b_end      = (const float*)d_in[13];
    float* out = (float*)d_out;

    prep_spect_kernel<<<(TOK*SPECT + 255)/256, 256>>>(spect);
    prep_gateB_kernel<<<(NLAYERS*CH2*KTOT + 255)/256, 256>>>(w_in, w_cond);
    prep_resB_kernel<<<((NLAYERS-1)*CH2*CH + CH*CH + 255)/256, 256>>>(w_res, w_res_last);
    start_kernel<<<(TOK*CH + 255)/256, 256>>>(audio, w_start, b_start);

    for (int l = 0; l < NLAYERS; l++) {
        gate_kernel<<<dim3(TOK/128, 4), 256>>>(
            b_in + (size_t)l*CH2, b_cond + (size_t)l*CH2, l, 1 << l);
        if (l < NLAYERS - 1) {
            res_kernel<<<dim3(TOK/128, 4), 256>>>(b_res + (size_t)l*CH2, l, 0);
        } else {
            res_kernel<<<dim3(TOK/128, 2), 256>>>(b_res_last, l, 1);
        }
    }

    end_kernel<<<(TOK*8 + 255)/256, 256>>>(w_end, b_end, out);
}

// round 17
// speedup vs baseline: 1.5890x; 1.5890x over previous
#include <cuda_runtime.h>
#include <cuda_fp16.h>
#include <math.h>

#define TLEN   4096
#define TOK    32768
#define CH     256
#define CH2    512
#define SPECT  640
#define KCONV  768
#define KTOT   1408
#define NLAYERS 12
#define SA     24          // smem k-stride (elems), padded vs. bank conflicts

typedef unsigned int u32;

// ------------------------- device scratch (alloc-free rule) -----------------
__device__ float g_started[TOK*CH];
__device__ float g_skip[TOK*CH];
__device__ __half g_sh[TOK*CH],   g_sl[TOK*CH];     // started hi/lo (fp16)
__device__ __half g_ah[TOK*CH],   g_al[TOK*CH];     // activated hi/lo
__device__ __half g_xh[TOK*SPECT],g_xl[TOK*SPECT];  // spect hi/lo
__device__ __half g_bgh[NLAYERS*CH2*KTOT];          // gate W^T [l][n][k], fp16
__device__ __half g_brh[(NLAYERS-1)*CH2*CH];        // res W^T
__device__ __half g_blh[CH*CH];                     // last res W^T

__device__ __forceinline__ void split2h(float v, __half& h, __half& l){
    h = __float2half(v);
    l = __float2half(v - __half2float(h));
}
__device__ __forceinline__ u32 smem_u32(const void* p){
    u32 a; asm("{ .reg .u64 t; cvta.to.shared.u64 t, %1; cvt.u32.u64 %0, t; }"
               : "=r"(a) : "l"(p));
    return a;
}
__device__ __forceinline__ void mma_f16(float* c, const u32* a, const u32* b){
    asm volatile(
      "mma.sync.aligned.m16n8k16.row.col.f32.f16.f16.f32 "
      "{%0,%1,%2,%3}, {%4,%5,%6,%7}, {%8,%9}, {%0,%1,%2,%3};\n"
      : "+f"(c[0]), "+f"(c[1]), "+f"(c[2]), "+f"(c[3])
      : "r"(a[0]), "r"(a[1]), "r"(a[2]), "r"(a[3]), "r"(b[0]), "r"(b[1]));
}
__device__ __forceinline__ void cpa16(u32 dst, const void* src, u32 sz){
    asm volatile("cp.async.cg.shared.global [%0], [%1], 16, %2;\n"
                 :: "r"(dst), "l"(src), "r"(sz));
}
__device__ __forceinline__ void cpa_commit(){ asm volatile("cp.async.commit_group;\n"); }
__device__ __forceinline__ void cpa_wait(){ asm volatile("cp.async.wait_group 0;\n"); }

// ------------------------------ prep kernels --------------------------------
__global__ void prep_spect_kernel(const float* __restrict__ spect){
    int i = blockIdx.x*256 + threadIdx.x;
    if (i >= TOK*SPECT) return;
    split2h(spect[i], g_xh[i], g_xl[i]);
}
__global__ void prep_gateB_kernel(const float* __restrict__ w_in,
                                  const float* __restrict__ w_cond){
    long i = (long)blockIdx.x*256 + threadIdx.x;
    if (i >= (long)NLAYERS*CH2*KTOT) return;
    int kk = (int)(i % KTOT);
    long r = i / KTOT;
    int n  = (int)(r % CH2);
    int l  = (int)(r / CH2);
    float v = (kk < KCONV) ? w_in[((size_t)l*KCONV + kk)*CH2 + n]
                           : w_cond[((size_t)l*SPECT + (kk-KCONV))*CH2 + n];
    g_bgh[i] = __float2half(v);
}
__global__ void prep_resB_kernel(const float* __restrict__ w_res,
                                 const float* __restrict__ w_res_last){
    int i = blockIdx.x*256 + threadIdx.x;
    const int NRES = (NLAYERS-1)*CH2*CH;
    if (i < NRES){
        int k = i % CH;
        int r = i / CH;
        int n = r % CH2;
        int l = r / CH2;
        g_brh[i] = __float2half(w_res[((size_t)l*CH + k)*CH2 + n]);
    } else if (i < NRES + CH*CH){
        int j = i - NRES;
        int k = j % CH;
        int n = j / CH;
        g_blh[j] = __float2half(w_res_last[(size_t)k*CH + n]);
    }
}

// ------------------------------ start kernel --------------------------------
__global__ void start_kernel(const float* __restrict__ audio,
                             const float* __restrict__ w_start,
                             const float* __restrict__ b_start)
{
    int idx = blockIdx.x*256 + threadIdx.x;
    if (idx >= TOK*CH) return;
    int token = idx >> 8;
    int c     = idx & 255;
    const float* a = audio + token*4;
    float v = b_start[c];
    v += a[0]*w_start[0*CH + c];
    v += a[1]*w_start[1*CH + c];
    v += a[2]*w_start[2*CH + c];
    v += a[3]*w_start[3*CH + c];
    g_started[idx] = v;
    split2h(v, g_sh[idx], g_sl[idx]);
    g_skip[idx] = 0.f;
}

// ------------------------------ gate kernel ---------------------------------
// Block: 128 tokens x (64 tanh cols + 64 sig cols). K=1408 = 88 chunks of 16.
// Two uniform mainloops (no in-loop branch):
//   conv stages 0..47:  2-limb  acc += Ahi*Bh + Alo*Bh
//   cond stages 48..87: 1-limb  acc += Ahi*Bh   (spect is static input)
__global__ void __launch_bounds__(256,2) gate_kernel(
    const float* __restrict__ b_in, const float* __restrict__ b_cond,
    int layer, int dil)
{
    __shared__ __half sm[2][3][128*SA]; // [buf][Ah,Al,Bh][row*SA+k]

    int tid = threadIdx.x;
    int m0 = blockIdx.x*128;
    int n0 = blockIdx.y*64;          // tanh column base (0,64,128,192)
    int warp = tid>>5, lane = tid&31;
    int wm = warp>>1, wn = warp&1;
    int g = lane>>2,  tig = lane&3;

    u32 sbase = smem_u32(sm);

    // tile-load mapping: 2 threads per row, each 16B (8 halves) per plane
    int lrow = tid>>1, lhalf = tid&1;
    int token = m0 + lrow;
    int bb = token>>12, tt = token&(TLEN-1);
    int cw = lrow>>6, cc2 = lrow&63;
    int ncol = (cc2<32) ? (n0 + cw*32 + cc2) : (256 + n0 + cw*32 + (cc2-32));
    const __half* browh = g_bgh + ((size_t)layer*CH2 + ncol)*KTOT + lhalf*8;

    // precomputed per-thread A sources: 3 taps + spect
    const __half* tapH[3];
    const __half* tapL[3];
    u32 tapSz[3];
    #pragma unroll
    for (int t=0;t<3;t++){
        int ts = tt + (t-1)*dil;
        bool ok = ((unsigned)ts < (unsigned)TLEN);
        int tok2 = (bb<<12) + (ok ? ts : 0);
        tapH[t] = g_sh + ((size_t)tok2<<8) + lhalf*8;
        tapL[t] = g_sl + ((size_t)tok2<<8) + lhalf*8;
        tapSz[t] = ok ? 16u : 0u;
    }
    const __half* xH = g_xh + (size_t)token*SPECT + lhalf*8;

    const u32 PLB = 128*SA*2;
    u32 doff = (u32)(lrow*SA + lhalf*8)*2;

    auto load_tiles = [&](int kc, int buf){
        u32 pb = sbase + (u32)buf*3u*PLB;
        if (kc < 48){
            int tap = kc>>4;
            int ch  = (kc&15)<<4;
            cpa16(pb       + doff, tapH[tap] + ch, tapSz[tap]);
            cpa16(pb + PLB + doff, tapL[tap] + ch, tapSz[tap]);
        } else {
            int koff = (kc-48)<<4;
            cpa16(pb       + doff, xH + koff, 16u);
        }
        cpa16(pb + 2*PLB + doff, browh + (kc<<4), 16u);
        cpa_commit();
    };

    float acc[2][8][4];
    #pragma unroll
    for (int mt=0;mt<2;mt++)
        #pragma unroll
        for (int j=0;j<8;j++)
            #pragma unroll
            for (int r2=0;r2<4;r2++) acc[mt][j][r2]=0.f;

    load_tiles(0,0);
    const int NKC = KTOT/16;    // 88
    const int NCV = KCONV/16;   // 48

    // ---- conv loop: uniform 2-limb body ----
    for (int kc=0; kc<NCV; kc++){
        cpa_wait(); __syncthreads();
        load_tiles(kc+1, (kc+1)&1);   // kc+1 <= 48 < NKC always
        int buf = kc&1;

        u32 fa[2][2][4]; // [limb][mtile][reg]
        #pragma unroll
        for (int mt=0; mt<2; mt++){
            int r0 = (wm*32 + mt*16 + g)*SA + 2*tig;
            const __half* ph = &sm[buf][0][r0];
            fa[0][mt][0] = *(const u32*)(ph);
            fa[0][mt][1] = *(const u32*)(ph + 8*SA);
            fa[0][mt][2] = *(const u32*)(ph + 8);
            fa[0][mt][3] = *(const u32*)(ph + 8*SA + 8);
            const __half* pl = &sm[buf][1][r0];
            fa[1][mt][0] = *(const u32*)(pl);
            fa[1][mt][1] = *(const u32*)(pl + 8*SA);
            fa[1][mt][2] = *(const u32*)(pl + 8);
            fa[1][mt][3] = *(const u32*)(pl + 8*SA + 8);
        }
        #pragma unroll
        for (int j=0; j<8; j++){
            int cr = (wn*64 + j*8 + g)*SA + 2*tig;
            const __half* pbh = &sm[buf][2][cr];
            u32 bh[2] = { *(const u32*)pbh, *(const u32*)(pbh+8) };
            mma_f16(acc[0][j], fa[0][0], bh);
            mma_f16(acc[1][j], fa[0][1], bh);
            mma_f16(acc[0][j], fa[1][0], bh);
            mma_f16(acc[1][j], fa[1][1], bh);
        }
    }

    // ---- cond loop: uniform 1-limb body ----
    for (int kc=NCV; kc<NKC; kc++){
        cpa_wait(); __syncthreads();
        if (kc+1 < NKC) load_tiles(kc+1, (kc+1)&1);
        int buf = kc&1;

        u32 fa0[2][4];
        #pragma unroll
        for (int mt=0; mt<2; mt++){
            int r0 = (wm*32 + mt*16 + g)*SA + 2*tig;
            const __half* ph = &sm[buf][0][r0];
            fa0[mt][0] = *(const u32*)(ph);
            fa0[mt][1] = *(const u32*)(ph + 8*SA);
            fa0[mt][2] = *(const u32*)(ph + 8);
            fa0[mt][3] = *(const u32*)(ph + 8*SA + 8);
        }
        #pragma unroll
        for (int j=0; j<8; j++){
            int cr = (wn*64 + j*8 + g)*SA + 2*tig;
            const __half* pbh = &sm[buf][2][cr];
            u32 bh[2] = { *(const u32*)pbh, *(const u32*)(pbh+8) };
            mma_f16(acc[0][j], fa0[0], bh);
            mma_f16(acc[1][j], fa0[1], bh);
        }
    }

    // epilogue: acc[mt][j] = tanh half, acc[mt][j+4] = matching sigmoid half
    #pragma unroll
    for (int mt=0; mt<2; mt++){
        #pragma unroll
        for (int j=0; j<4; j++){
            int ct = n0 + wn*32 + j*8 + 2*tig;
            float bT0 = b_in[ct]     + b_cond[ct];
            float bT1 = b_in[ct+1]   + b_cond[ct+1];
            float bS0 = b_in[ct+256] + b_cond[ct+256];
            float bS1 = b_in[ct+257] + b_cond[ct+257];
            #pragma unroll
            for (int h=0; h<2; h++){
                int row = m0 + wm*32 + mt*16 + g + h*8;
                float t0 = acc[mt][j][h*2+0] + bT0;
                float t1 = acc[mt][j][h*2+1] + bT1;
                float s0 = acc[mt][j+4][h*2+0] + bS0;
                float s1 = acc[mt][j+4][h*2+1] + bS1;
                float v0 = tanhf(t0) * (1.f/(1.f+__expf(-s0)));
                float v1 = tanhf(t1) * (1.f/(1.f+__expf(-s1)));
                __half h0,l0,h1,l1;
                split2h(v0,h0,l0); split2h(v1,h1,l1);
                size_t o = (size_t)row*CH + ct;
                __half2 vh; vh.x=h0; vh.y=h1;
                __half2 vl; vl.x=l0; vl.y=l1;
                *(__half2*)&g_ah[o] = vh;
                *(__half2*)&g_al[o] = vl;
            }
        }
    }
}

// ------------------------------ res kernel ----------------------------------
// rs = activated @ w + bias; cols<256 -> started update (+ re-split),
// cols>=256 -> skip accumulation. last: all 256 cols -> skip.
__global__ void __launch_bounds__(256,2) res_kernel(
    const float* __restrict__ bias, int layer, int last)
{
    __shared__ __half sm[2][3][128*SA];

    int tid = threadIdx.x;
    int m0 = blockIdx.x*128;
    int n0 = blockIdx.y*128;
    int warp = tid>>5, lane = tid&31;
    int wm = warp>>1, wn = warp&1;
    int g = lane>>2,  tig = lane&3;

    u32 sbase = smem_u32(sm);

    int lrow = tid>>1, lhalf = tid&1;
    int token = m0 + lrow;
    int ncol = n0 + lrow;
    const __half* browh = (last ? (g_blh + (size_t)ncol*CH)
                                : (g_brh + ((size_t)layer*CH2 + ncol)*CH)) + lhalf*8;
    const __half* arh = g_ah + (size_t)token*CH + lhalf*8;
    const __half* arl = g_al + (size_t)token*CH + lhalf*8;

    const u32 PLB = 128*SA*2;
    u32 doff = (u32)(lrow*SA + lhalf*8)*2;

    auto load_tiles = [&](int kc, int buf){
        u32 pb = sbase + (u32)buf*3u*PLB;
        int kb = kc<<4;
        cpa16(pb         + doff, arh + kb, 16u);
        cpa16(pb + PLB   + doff, arl + kb, 16u);
        cpa16(pb + 2*PLB + doff, browh + kb, 16u);
        cpa_commit();
    };

    float acc[2][8][4];
    #pragma unroll
    for (int mt=0;mt<2;mt++)
        #pragma unroll
        for (int j=0;j<8;j++)
            #pragma unroll
            for (int r2=0;r2<4;r2++) acc[mt][j][r2]=0.f;

    load_tiles(0,0);
    const int NKC = CH/16;
    for (int kc=0; kc<NKC; kc++){
        cpa_wait(); __syncthreads();
        if (kc+1 < NKC) load_tiles(kc+1, (kc+1)&1);
        int buf = kc&1;

        u32 fa[2][2][4];
        #pragma unroll
        for (int mt=0; mt<2; mt++){
            int r0 = (wm*32 + mt*16 + g)*SA + 2*tig;
            const __half* ph = &sm[buf][0][r0];
            fa[0][mt][0] = *(const u32*)(ph);
            fa[0][mt][1] = *(const u32*)(ph + 8*SA);
            fa[0][mt][2] = *(const u32*)(ph + 8);
            fa[0][mt][3] = *(const u32*)(ph + 8*SA + 8);
            const __half* pl = &sm[buf][1][r0];
            fa[1][mt][0] = *(const u32*)(pl);
            fa[1][mt][1] = *(const u32*)(pl + 8*SA);
            fa[1][mt][2] = *(const u32*)(pl + 8);
            fa[1][mt][3] = *(const u32*)(pl + 8*SA + 8);
        }
        #pragma unroll
        for (int j=0; j<8; j++){
            int cr = (wn*64 + j*8 + g)*SA + 2*tig;
            const __half* pbh = &sm[buf][2][cr];
            u32 bh[2] = { *(const u32*)pbh, *(const u32*)(pbh+8) };
            mma_f16(acc[0][j], fa[0][0], bh);
            mma_f16(acc[1][j], fa[0][1], bh);
            mma_f16(acc[0][j], fa[1][0], bh);
            mma_f16(acc[1][j], fa[1][1], bh);
        }
    }

    #pragma unroll
    for (int mt=0; mt<2; mt++){
        #pragma unroll
        for (int j=0; j<8; j++){
            int col = n0 + wn*64 + j*8 + 2*tig;
            float b0v = bias[col], b1v = bias[col+1];
            #pragma unroll
            for (int h=0; h<2; h++){
                int row = m0 + wm*32 + mt*16 + g + h*8;
                float v0 = acc[mt][j][h*2+0] + b0v;
                float v1 = acc[mt][j][h*2+1] + b1v;
                if (last){
                    size_t o = (size_t)row*CH + col;
                    g_skip[o]   += v0;
                    g_skip[o+1] += v1;
                } else if (col < 256){
                    size_t o = (size_t)row*CH + col;
                    float s0 = g_started[o]   + v0;
                    float s1 = g_started[o+1] + v1;
                    g_started[o]   = s0;
                    g_started[o+1] = s1;
                    __half h0,l0,h1,l1;
                    split2h(s0,h0,l0); split2h(s1,h1,l1);
                    __half2 vh; vh.x=h0; vh.y=h1;
                    __half2 vl; vl.x=l0; vl.y=l1;
                    *(__half2*)&g_sh[o] = vh;
                    *(__half2*)&g_sl[o] = vl;
                } else {
                    size_t o = (size_t)row*CH + col - 256;
                    g_skip[o]   += v0;
                    g_skip[o+1] += v1;
                }
            }
        }
    }
}

// ------------------------------ end kernel ----------------------------------
__global__ void end_kernel(const float* __restrict__ w_end,
                           const float* __restrict__ b_end,
                           float* __restrict__ out)
{
    int idx = blockIdx.x*256 + threadIdx.x;
    if (idx >= TOK*8) return;
    int token = idx >> 3;
    int j     = idx & 7;
    const float* s = g_skip + (size_t)token*CH;
    float v = b_end[j];
    #pragma unroll 8
    for (int c = 0; c < CH; c++)
        v += s[c] * w_end[c*8 + j];
    out[idx] = v;
}

// ----------------------------------------------------------------------------
extern "C" void kernel_launch(void* const* d_in, const int* in_sizes, int n_in,
                              void* d_out, int out_size)
{
    const float* audio      = (const float*)d_in[0];
    const float* spect      = (const float*)d_in[1];
    const float* w_start    = (const float*)d_in[2];
    const float* b_start    = (const float*)d_in[3];
    const float* w_in       = (const float*)d_in[4];
    const float* b_in       = (const float*)d_in[5];
    const float* w_cond     = (const float*)d_in[6];
    const float* b_cond     = (const float*)d_in[7];
    const float* w_res      = (const float*)d_in[8];
    const float* b_res      = (const float*)d_in[9];
    const float* w_res_last = (const float*)d_in[10];
    const float* b_res_last = (const float*)d_in[11];
    const float* w_end      = (const float*)d_in[12];
    const float* b_end      = (const float*)d_in[13];
    float* out = (float*)d_out;

    prep_spect_kernel<<<(TOK*SPECT + 255)/256, 256>>>(spect);
    prep_gateB_kernel<<<(NLAYERS*CH2*KTOT + 255)/256, 256>>>(w_in, w_cond);
    prep_resB_kernel<<<((NLAYERS-1)*CH2*CH + CH*CH + 255)/256, 256>>>(w_res, w_res_last);
    start_kernel<<<(TOK*CH + 255)/256, 256>>>(audio, w_start, b_start);

    for (int l = 0; l < NLAYERS; l++) {
        gate_kernel<<<dim3(TOK/128, 4), 256>>>(
            b_in + (size_t)l*CH2, b_cond + (size_t)l*CH2, l, 1 << l);
        if (l < NLAYERS - 1) {
            res_kernel<<<dim3(TOK/128, 4), 256>>>(b_res + (size_t)l*CH2, l, 0);
        } else {
            res_kernel<<<dim3(TOK/128, 2), 256>>>(b_res_last, l, 1);
        }
    }

    end_kernel<<<(TOK*8 + 255)/256, 256>>>(w_end, b_end, out);
}